// round 16
// baseline (speedup 1.0000x reference)
#include <cuda_runtime.h>
#include <cuda_fp16.h>
#include <cstdint>

#define BB 2
#define TT 4096
#define EE 768
#define HH 12
#define DD 64
#define E3 (3*EE)
#define MTOT (BB*TT)

// Scratch (allocation-free rule: __device__ globals)
__device__ __half g_xh [(size_t)MTOT*EE];   // x in fp16
__device__ __half g_qkv[(size_t)MTOT*E3];   // [B,T,3E] fp16
__device__ __half g_y  [(size_t)MTOT*EE];   // attention out fp16
__device__ __half g_wt1[(size_t)E3*EE];     // W_attn^T [2304][768] fp16 (K-major)
__device__ __half g_wt2[(size_t)EE*EE];     // W_proj^T [768][768]  fp16 (K-major)

// ---------------------------------------------------------------------------
// helpers
// ---------------------------------------------------------------------------
__device__ __forceinline__ uint32_t smem_u32(const void* p) {
    uint32_t a;
    asm("{ .reg .u64 t; cvta.to.shared.u64 t, %1; cvt.u32.u64 %0, t; }" : "=r"(a) : "l"(p));
    return a;
}
__device__ __forceinline__ void cp16(uint32_t saddr, const void* g) {
    asm volatile("cp.async.cg.shared.global [%0], [%1], 16;" :: "r"(saddr), "l"(g));
}
#define CP_COMMIT() asm volatile("cp.async.commit_group;" ::: "memory")
#define CP_WAIT0()  asm volatile("cp.async.wait_group 0;" ::: "memory")
#define CP_WAIT1()  asm volatile("cp.async.wait_group 1;" ::: "memory")

__device__ __forceinline__ unsigned h2bits(__half2 h) { return *(unsigned*)&h; }
__device__ __forceinline__ unsigned packf(float a, float b) {
    __half2 h = __floats2half2_rn(a, b);
    return *(unsigned*)&h;
}

__device__ __forceinline__ void ldsm4(uint32_t addr, unsigned* r) {
    asm volatile("ldmatrix.sync.aligned.m8n8.x4.shared.b16 {%0,%1,%2,%3}, [%4];"
        : "=r"(r[0]), "=r"(r[1]), "=r"(r[2]), "=r"(r[3]) : "r"(addr));
}
__device__ __forceinline__ void ldsm4t(uint32_t addr, unsigned* r) {
    asm volatile("ldmatrix.sync.aligned.m8n8.x4.trans.shared.b16 {%0,%1,%2,%3}, [%4];"
        : "=r"(r[0]), "=r"(r[1]), "=r"(r[2]), "=r"(r[3]) : "r"(addr));
}

#define MMA_F16(c, a0, a1, a2, a3, b0, b1)                                    \
    asm volatile(                                                             \
        "mma.sync.aligned.m16n8k16.row.col.f32.f16.f16.f32 "                  \
        "{%0,%1,%2,%3},{%4,%5,%6,%7},{%8,%9},{%0,%1,%2,%3};"                  \
        : "+f"((c)[0]), "+f"((c)[1]), "+f"((c)[2]), "+f"((c)[3])              \
        : "r"(a0), "r"(a1), "r"(a2), "r"(a3), "r"(b0), "r"(b1))

// ---------------------------------------------------------------------------
// prep: one launch: x->fp16 (4 chunks/block) + both weight transposes
// ---------------------------------------------------------------------------
#define NB_F2H 1536              // 6144/4 : each block handles 4 strided chunks
#define NB_T1  1728
#define NB_T2  576

__global__ void prep_kernel(const float* __restrict__ x,
                            const float* __restrict__ W1,
                            const float* __restrict__ W2,
                            __half* __restrict__ xh,
                            __half* __restrict__ wt1,
                            __half* __restrict__ wt2)
{
    const int bid = blockIdx.x;
    const int tid = threadIdx.x;
    if (bid < NB_F2H) {
#pragma unroll
        for (int j = 0; j < 4; j++) {
            int i = (((bid + j * NB_F2H) * 256) + tid) * 4;
            float4 v = *(const float4*)(x + i);
            uint2 u = { packf(v.x, v.y), packf(v.z, v.w) };
            *(uint2*)(xh + i) = u;
        }
    } else {
        __shared__ __half t[32][33];
        const float* W; __half* Wt; int N, b;
        if (bid < NB_F2H + NB_T1) { W = W1; Wt = wt1; N = E3; b = bid - NB_F2H; }
        else                      { W = W2; Wt = wt2; N = EE; b = bid - NB_F2H - NB_T1; }
        const int K = EE;
        const int nbx = N / 32;
        const int n0 = (b % nbx) * 32, k0 = (b / nbx) * 32;
        const int tx = tid & 31, ty = tid >> 5;
#pragma unroll
        for (int i = 0; i < 32; i += 8)
            t[ty + i][tx] = __float2half(W[(size_t)(k0 + ty + i) * N + n0 + tx]);
        __syncthreads();
#pragma unroll
        for (int i = 0; i < 32; i += 8)
            Wt[(size_t)(n0 + ty + i) * K + k0 + tx] = t[tx][ty + i];
    }
}

// ---------------------------------------------------------------------------
// FP16 GEMM: C[M,N] = A[M,K] @ Wt[N,K]^T + bias
// Tile 128x128, BK=64, 3-stage cp.async pipeline, 256 threads (8 warps),
// warp tile 32x64, ldmatrix fragments with B ring.
// ---------------------------------------------------------------------------
#define GP 72
#define GA(s) ((s) * 9216)
#define GEMM_SMEM 110592               // (27648 + 3*9216) halves * 2

template<int HALF_OUT>
__global__ __launch_bounds__(256, 2) void gemm_f16(
    const __half* __restrict__ A, const __half* __restrict__ Bt,
    const float* __restrict__ bias, void* __restrict__ Cv,
    int M, int N, int K)
{
    extern __shared__ __half sh[];
    const uint32_t sbase = smem_u32(sh);
    const int tid  = threadIdx.x;
    const int lane = tid & 31;
    const int warp = tid >> 5;
    const int grp  = lane >> 2;
    const int tid4 = lane & 3;
    const int wm = warp & 3;
    const int wn = warp >> 2;
    const int rowBase = blockIdx.y * 128;
    const int colBase = blockIdx.x * 128;

    const int lr = lane & 7, lt = lane >> 3;
    const uint32_t aoff0 = ((wm * 32 +      (lt & 1) * 8 + lr) * GP + (lt >> 1) * 8) * 2;
    const uint32_t aoff1 = ((wm * 32 + 16 + (lt & 1) * 8 + lr) * GP + (lt >> 1) * 8) * 2;
    const uint32_t boff0 = ((wn * 64 + (lt >> 1) * 8 + lr) * GP + (lt & 1) * 8) * 2;

    float acc[2][8][4];
#pragma unroll
    for (int mt = 0; mt < 2; mt++)
#pragma unroll
        for (int nt = 0; nt < 8; nt++)
#pragma unroll
            for (int c = 0; c < 4; c++) acc[mt][nt][c] = 0.f;

    const int nc = K / 64;

#define GFILL(c_, st_) do {                                                            \
    const int k0_ = (c_) * 64;                                                         \
    _Pragma("unroll")                                                                  \
    for (int i_ = 0; i_ < 4; i_++) {                                                   \
        int idx_ = tid + 256 * i_;                                                     \
        int m_ = idx_ >> 3, kc_ = (idx_ & 7) * 8;                                      \
        cp16(sbase + (GA(st_) + m_ * GP + kc_) * 2,                                    \
             A + (size_t)(rowBase + m_) * K + k0_ + kc_);                              \
        cp16(sbase + (27648 + (st_) * 9216 + m_ * GP + kc_) * 2,                       \
             Bt + (size_t)(colBase + m_) * K + k0_ + kc_);                             \
    }                                                                                  \
    CP_COMMIT();                                                                       \
} while (0)

    GFILL(0, 0);
    GFILL(1, 1);

    for (int c = 0; c < nc; c++) {
        if (c + 2 < nc) CP_WAIT1(); else CP_WAIT0();
        __syncthreads();
        if (c + 2 < nc) GFILL(c + 2, (c + 2) % 3);

        const int s = c % 3;
        const uint32_t baseA = sbase + GA(s) * 2;
        const uint32_t baseB = sbase + (27648 + s * 9216) * 2;

        unsigned afr[2][2][4];
        ldsm4(baseA + aoff0, afr[0][0]);
        ldsm4(baseA + aoff1, afr[0][1]);
        unsigned bb[3][4];
        ldsm4(baseB + boff0,                 bb[0]);
        ldsm4(baseB + boff0 + (16 * GP * 2), bb[1]);

#pragma unroll
        for (int t = 0; t < 16; t++) {
            const int kb = t >> 2, ntp = t & 3, cur = kb & 1;
            if (ntp == 0 && kb < 3) {
                ldsm4(baseA + aoff0 + (kb + 1) * 32, afr[cur ^ 1][0]);
                ldsm4(baseA + aoff1 + (kb + 1) * 32, afr[cur ^ 1][1]);
            }
            if (t + 2 < 16) {
                const int t2 = t + 2;
                ldsm4(baseB + boff0 + (t2 & 3) * (16 * GP * 2) + (t2 >> 2) * 32,
                      bb[t2 % 3]);
            }
            const unsigned* aa0 = afr[cur][0];
            const unsigned* aa1 = afr[cur][1];
            const unsigned* cc  = bb[t % 3];
            MMA_F16(acc[0][2 * ntp],     aa0[0], aa0[1], aa0[2], aa0[3], cc[0], cc[1]);
            MMA_F16(acc[0][2 * ntp + 1], aa0[0], aa0[1], aa0[2], aa0[3], cc[2], cc[3]);
            MMA_F16(acc[1][2 * ntp],     aa1[0], aa1[1], aa1[2], aa1[3], cc[0], cc[1]);
            MMA_F16(acc[1][2 * ntp + 1], aa1[0], aa1[1], aa1[2], aa1[3], cc[2], cc[3]);
        }
    }
#undef GFILL

    // epilogue: + bias
#pragma unroll
    for (int mt = 0; mt < 2; mt++) {
        int r0 = rowBase + wm * 32 + mt * 16 + grp;
        int r1 = r0 + 8;
#pragma unroll
        for (int nt = 0; nt < 8; nt++) {
            int col = colBase + wn * 64 + nt * 8 + 2 * tid4;
            float bx = bias[col], by = bias[col + 1];
            if (HALF_OUT) {
                __half* C = (__half*)Cv;
                *(unsigned*)&C[(size_t)r0 * N + col] = packf(acc[mt][nt][0] + bx, acc[mt][nt][1] + by);
                *(unsigned*)&C[(size_t)r1 * N + col] = packf(acc[mt][nt][2] + bx, acc[mt][nt][3] + by);
            } else {
                float* C = (float*)Cv;
                float2 o0 = { acc[mt][nt][0] + bx, acc[mt][nt][1] + by };
                float2 o1 = { acc[mt][nt][2] + bx, acc[mt][nt][3] + by };
                *(float2*)&C[(size_t)r0 * N + col] = o0;
                *(float2*)&C[(size_t)r1 * N + col] = o1;
            }
        }
    }
}

// ---------------------------------------------------------------------------
// Flash attention: fp16 MMA, register P, log2-domain half2 softmax,
// hoisted Q fragments, tensor-core row sums, per-warp diagonal chunk skipping.
// 3-stage cp.async K/V pipeline. 256 threads = 8 warps (16 q rows each).
// ---------------------------------------------------------------------------
#define AKo 9216
#define AVo 23040
#define ATTN_SMEM 73728

#define ATTN_FILL(j_, st_) do {                                                        \
    const int kr_ = (j_) * 64;                                                         \
    _Pragma("unroll")                                                                  \
    for (int i_ = 0; i_ < 2; i_++) {                                                   \
        int idx_ = tid + 256 * i_;                                                     \
        int r_ = idx_ >> 3, c16_ = (idx_ & 7) * 8;                                     \
        cp16(sbase + (AKo + (st_) * 4608 + r_ * GP + c16_) * 2,                        \
             &g_qkv[base + (size_t)(kr_ + r_) * E3 + EE + c16_]);                      \
        cp16(sbase + (AVo + (st_) * 4608 + r_ * GP + c16_) * 2,                        \
             &g_qkv[base + (size_t)(kr_ + r_) * E3 + 2 * EE + c16_]);                  \
    }                                                                                  \
    CP_COMMIT();                                                                       \
} while (0)

__global__ __launch_bounds__(256, 2) void attn_f16_kernel()
{
    extern __shared__ __half sh[];
    const uint32_t sbase = smem_u32(sh);

    const int tid  = threadIdx.x;
    const int lane = tid & 31;
    const int warp = tid >> 5;
    const int grp  = lane >> 2;
    const int tid4 = lane & 3;
    const int w16  = warp * 16;

    const int qt = (int)gridDim.x - 1 - (int)blockIdx.x;   // heaviest tiles first
    const int bh = blockIdx.y;
    const int b = bh / HH, h = bh % HH;
    const int q0 = qt * 128;

    const size_t base = (size_t)b * TT * E3 + (size_t)h * DD;

    const int lr = lane & 7, lt = lane >> 3;
    const uint32_t qoff  = ((w16 + (lt & 1) * 8 + lr) * GP + (lt >> 1) * 8) * 2;
    const uint32_t koff0 = (((lt >> 1) * 8 + lr) * GP + (lt & 1) * 8) * 2;
    const uint32_t voff0 = (((lt & 1) * 8 + lr) * GP + (lt >> 1) * 8) * 2;

    // load Q tile (128x64), scale 0.125*log2(e) folded in (log2-domain scores)
    const float SC = 0.125f * 1.4426950408889634f;
#pragma unroll
    for (int i = tid; i < 2048; i += 256) {
        int r = i >> 4, c4 = (i & 15) * 4;
        uint2 u = *(const uint2*)&g_qkv[base + (size_t)(q0 + r) * E3 + c4];
        float2 f0 = __half22float2(*(__half2*)&u.x);
        float2 f1 = __half22float2(*(__half2*)&u.y);
        uint2 o = { packf(f0.x * SC, f0.y * SC), packf(f1.x * SC, f1.y * SC) };
        *(uint2*)&sh[r * GP + c4] = o;
    }

    const int njt = 2 * qt + 2;
    ATTN_FILL(0, 0);
    if (njt > 1) ATTN_FILL(1, 1);

    __syncthreads();                 // Q stores visible before hoisted ldsm

    // hoist Q fragments: 16 regs, reused for every k tile
    unsigned qfr[4][4];
#pragma unroll
    for (int kb = 0; kb < 4; kb++) ldsm4(sbase + qoff + kb * 32, qfr[kb]);

    float oacc[8][4];
    float mrow[2] = { -1e30f, -1e30f };
    float lrow[2] = { 0.f, 0.f };    // exact per-lane row sums (from sum-MMA)
#pragma unroll
    for (int nt = 0; nt < 8; nt++)
#pragma unroll
        for (int c = 0; c < 4; c++) oacc[nt][c] = 0.f;

    const unsigned ONE2 = 0x3C003C00u;   // half2(1.0, 1.0)
    const int rmax = q0 + w16 + 15;      // last valid row for this warp

    for (int jt = 0; jt < njt; jt++) {
        const int k0 = jt * 64;
        if (jt + 2 < njt) CP_WAIT1(); else CP_WAIT0();
        __syncthreads();
        if (jt + 2 < njt) ATTN_FILL(jt + 2, (jt + 2) % 3);

        const bool active = (k0 <= rmax);
        if (active) {
            const int st = jt % 3;
            const uint32_t baseK = sbase + (AKo + st * 4608) * 2;
            const uint32_t baseV = sbase + (AVo + st * 4608) * 2;
            // valid 16-key chunks for this warp in this tile (1..4)
            const int nlim = (k0 + 63 <= rmax) ? 4 : (((rmax - k0) >> 4) + 1);

            // ---- S = Q K^T (log2 domain), skipping fully-masked chunks ----
            float sacc[8][4];
#pragma unroll
            for (int nt = 0; nt < 8; nt++)
#pragma unroll
                for (int c = 0; c < 4; c++) sacc[nt][c] = 0.f;

#pragma unroll
            for (int kk = 0; kk < 4; kk++) {
                const unsigned* q = qfr[kk];
#pragma unroll
                for (int ntp = 0; ntp < 4; ntp++) {
                    if (ntp < nlim) {
                        unsigned cc[4];
                        ldsm4(baseK + koff0 + ntp * (16 * GP * 2) + kk * 32, cc);
                        MMA_F16(sacc[2 * ntp],     q[0], q[1], q[2], q[3], cc[0], cc[1]);
                        MMA_F16(sacc[2 * ntp + 1], q[0], q[1], q[2], q[3], cc[2], cc[3]);
                    }
                }
            }

            // causal mask (within valid chunks only)
            if (k0 + 63 > q0 + w16) {
#pragma unroll
                for (int nt = 0; nt < 8; nt++) {
                    if (nt < 2 * nlim) {
#pragma unroll
                        for (int c = 0; c < 4; c++) {
                            int row = q0 + w16 + grp + 8 * (c >> 1);
                            int col = k0 + nt * 8 + 2 * tid4 + (c & 1);
                            if (col > row) sacc[nt][c] = -1e30f;
                        }
                    }
                }
            }

            // ---- online softmax (base 2); P = h2exp2 -> fp16 A-fragments ----
            unsigned pr[8][2];
            float alpha[2];
#pragma unroll
            for (int p = 0; p < 2; p++) {
                float mx = -1e30f;
#pragma unroll
                for (int nt = 0; nt < 8; nt++)
                    if (nt < 2 * nlim)
                        mx = fmaxf(mx, fmaxf(sacc[nt][2 * p], sacc[nt][2 * p + 1]));
                mx = fmaxf(mx, __shfl_xor_sync(0xffffffffu, mx, 1));
                mx = fmaxf(mx, __shfl_xor_sync(0xffffffffu, mx, 2));
                float mnew = fmaxf(mrow[p], mx);
                alpha[p] = exp2f(mrow[p] - mnew);
                mrow[p] = mnew;
#pragma unroll
                for (int nt = 0; nt < 8; nt++) {
                    if (nt < 2 * nlim) {
                        __half2 d = __floats2half2_rn(sacc[nt][2 * p]     - mnew,
                                                      sacc[nt][2 * p + 1] - mnew);
                        pr[nt][p] = h2bits(h2exp2(d));
                    }
                }
#pragma unroll
                for (int nt = 0; nt < 8; nt++) {
                    oacc[nt][2 * p]     *= alpha[p];
                    oacc[nt][2 * p + 1] *= alpha[p];
                }
            }

            // ---- row sums via tensor core: lsum = P @ ones ----
            float ssum[4] = { 0.f, 0.f, 0.f, 0.f };
#pragma unroll
            for (int s4 = 0; s4 < 4; s4++)
                if (s4 < nlim)
                    MMA_F16(ssum, pr[2 * s4][0], pr[2 * s4][1],
                            pr[2 * s4 + 1][0], pr[2 * s4 + 1][1], ONE2, ONE2);
            lrow[0] = lrow[0] * alpha[0] + ssum[0];
            lrow[1] = lrow[1] * alpha[1] + ssum[2];

            // ---- O += P V (V via ldmatrix.trans), skipping zero-P chunks ----
#pragma unroll
            for (int s4 = 0; s4 < 4; s4++) {
                if (s4 < nlim) {
#pragma unroll
                    for (int ntp = 0; ntp < 4; ntp++) {
                        unsigned cc[4];
                        ldsm4t(baseV + voff0 + s4 * (16 * GP * 2) + ntp * 32, cc);
                        MMA_F16(oacc[2 * ntp],     pr[2 * s4][0], pr[2 * s4][1],
                                pr[2 * s4 + 1][0], pr[2 * s4 + 1][1], cc[0], cc[1]);
                        MMA_F16(oacc[2 * ntp + 1], pr[2 * s4][0], pr[2 * s4][1],
                                pr[2 * s4 + 1][0], pr[2 * s4 + 1][1], cc[2], cc[3]);
                    }
                }
            }
        }
    }

    // epilogue: lrow is already the exact full row sum in every lane
    float inv0 = 1.0f / lrow[0];
    float inv1 = 1.0f / lrow[1];
    int r0 = q0 + w16 + grp;
    int r1 = r0 + 8;
#pragma unroll
    for (int nt = 0; nt < 8; nt++) {
        int col = h * DD + nt * 8 + 2 * tid4;
        *(unsigned*)&g_y[((size_t)b * TT + r0) * EE + col] =
            packf(oacc[nt][0] * inv0, oacc[nt][1] * inv0);
        *(unsigned*)&g_y[((size_t)b * TT + r1) * EE + col] =
            packf(oacc[nt][2] * inv1, oacc[nt][3] * inv1);
    }
}

// ---------------------------------------------------------------------------
extern "C" void kernel_launch(void* const* d_in, const int* in_sizes, int n_in,
                              void* d_out, int out_size)
{
    const float* x      = (const float*)d_in[0];
    const float* W_attn = (const float*)d_in[1];
    const float* b_attn = (const float*)d_in[2];
    const float* W_proj = (const float*)d_in[3];
    const float* b_proj = (const float*)d_in[4];
    float* out = (float*)d_out;

    __half *xh, *qkv, *y, *wt1, *wt2;
    cudaGetSymbolAddress((void**)&xh,  g_xh);
    cudaGetSymbolAddress((void**)&qkv, g_qkv);
    cudaGetSymbolAddress((void**)&y,   g_y);
    cudaGetSymbolAddress((void**)&wt1, g_wt1);
    cudaGetSymbolAddress((void**)&wt2, g_wt2);

    cudaFuncSetAttribute((const void*)gemm_f16<1>,
                         cudaFuncAttributeMaxDynamicSharedMemorySize, GEMM_SMEM);
    cudaFuncSetAttribute((const void*)gemm_f16<0>,
                         cudaFuncAttributeMaxDynamicSharedMemorySize, GEMM_SMEM);
    cudaFuncSetAttribute(attn_f16_kernel,
                         cudaFuncAttributeMaxDynamicSharedMemorySize, ATTN_SMEM);

    // 0) prep: x -> fp16, weights -> fp16 K-major transpose
    prep_kernel<<<NB_F2H + NB_T1 + NB_T2, 256>>>(x, W_attn, W_proj, xh, wt1, wt2);

    // 1) QKV projection: [8192,768] @ [768,2304] + b  -> qkv (fp16)
    gemm_f16<1><<<dim3(E3 / 128, MTOT / 128), 256, GEMM_SMEM>>>(
        xh, wt1, b_attn, qkv, MTOT, E3, EE);

    // 2) causal flash attention -> y (fp16)
    attn_f16_kernel<<<dim3(TT / 128, BB * HH), 256, ATTN_SMEM>>>();

    // 3) output projection (128x128 tiles): -> out (fp32)
    gemm_f16<0><<<dim3(EE / 128, MTOT / 128), 256, GEMM_SMEM>>>(
        y, wt2, b_proj, out, MTOT, EE, EE);
}